// round 7
// baseline (speedup 1.0000x reference)
#include <cuda_runtime.h>
#include <cuda_fp16.h>
#include <math.h>
#include <stdint.h>

// Problem constants
#define DIM   1024
#define NB    64      // n_image == n_caption
#define NS    36      // regions
#define NL    32      // max caption length
#define MROWS (NB*NS)     // 2304 image rows
#define CROWS (NB*NL)     // 2048 caption rows

// ---------------- device scratch (no allocations allowed) ----------------
__device__ float  g_A[MROWS * CROWS];     // attn logits img . E    (2304x2048)
__device__ float  g_C[MROWS * CROWS];     // img . cap dots         (2304x2048)
__device__ float  g_G[NB * NS * NS];      // per-image gram         (64x36x36)
__device__ float  g_w1[CROWS];            // caption word norms     (2048)
__device__ __half g_Ihi[MROWS * DIM], g_Ilo[MROWS * DIM];   // images split
__device__ __half g_Phi[CROWS * DIM], g_Plo[CROWS * DIM];   // captions split
__device__ __half g_Whi[DIM * DIM],   g_Wlo[DIM * DIM];     // W_g split
__device__ __half g_Ehi[CROWS * DIM], g_Elo[CROWS * DIM];   // energy split

__device__ __forceinline__ uint32_t smem_u32(const void* p) {
    uint32_t a;
    asm("{ .reg .u64 t; cvta.to.shared.u64 t, %1; cvt.u32.u64 %0, t; }" : "=r"(a) : "l"(p));
    return a;
}

#define LDSM_X4(r0, r1, r2, r3, addr) \
    asm volatile("ldmatrix.sync.aligned.m8n8.x4.shared.b16 {%0,%1,%2,%3}, [%4];" \
                 : "=r"(r0), "=r"(r1), "=r"(r2), "=r"(r3) : "r"(addr))

#define MMA16816(c0, c1, c2, c3, a0, a1, a2, a3, b0, b1) \
    asm volatile("mma.sync.aligned.m16n8k16.row.col.f32.f16.f16.f32 " \
                 "{%0,%1,%2,%3}, {%4,%5,%6,%7}, {%8,%9}, {%0,%1,%2,%3};" \
                 : "+f"(c0), "+f"(c1), "+f"(c2), "+f"(c3) \
                 : "r"(a0), "r"(a1), "r"(a2), "r"(a3), "r"(b0), "r"(b1))

#define CP_ASYNC16(dst, src) \
    asm volatile("cp.async.cg.shared.global [%0], [%1], 16;" :: "r"(dst), "l"(src))
#define CP_COMMIT() asm volatile("cp.async.commit_group;")
#define CP_WAIT1()  asm volatile("cp.async.wait_group 1;")
#define CP_WAIT0()  asm volatile("cp.async.wait_group 0;")

// =========================================================================
// fp32 -> (hi, lo) fp16 split kernel
// =========================================================================
__global__ __launch_bounds__(256)
void split_kernel(const float4* __restrict__ x, __half2* __restrict__ hi,
                  __half2* __restrict__ lo, int n4) {
    int idx = blockIdx.x * 256 + threadIdx.x;
    if (idx >= n4) return;
    float4 v = x[idx];
    __half2 h0 = __floats2half2_rn(v.x, v.y);
    __half2 h1 = __floats2half2_rn(v.z, v.w);
    float2 f0 = __half22float2(h0);
    float2 f1 = __half22float2(h1);
    hi[2 * idx]     = h0;
    hi[2 * idx + 1] = h1;
    lo[2 * idx]     = __floats2half2_rn(v.x - f0.x, v.y - f0.y);
    lo[2 * idx + 1] = __floats2half2_rn(v.z - f1.x, v.w - f1.y);
}

// =========================================================================
// Split-fp16 tensor-core NT GEMM, cp.async double-buffered, 2 CTAs/SM.
// D[m][n] = sum_k (Ahi+Alo)[m][k]*(Bhi+Blo)[n][k], dropping lo*lo.
// CTA tile 128x128, 8 warps, warp tile 64x32, K-chunk 32, 2-stage pipeline.
// MODE 0: write fp32 D.  MODE 1: write split fp16 (Dhi, Dlo).
// =========================================================================
#define SROWB 80                   // smem row stride bytes (32 halves + 16B pad)
#define TILE  (128 * SROWB)        // 10240 B per operand tile
#define STAGE (4 * TILE)           // Ah, Al, Bh, Bl  = 40960 B
#define GEMM_SMEM (2 * STAGE)      // 81920 B  -> 2 CTAs/SM

template<int MODE>
__global__ __launch_bounds__(256, 2)
void gemm_tc_kernel(const __half* __restrict__ Ahi, const __half* __restrict__ Alo,
                    const __half* __restrict__ Bhi, const __half* __restrict__ Blo,
                    float* __restrict__ Df, __half* __restrict__ Dhi, __half* __restrict__ Dlo,
                    int M, int N, int K) {
    extern __shared__ char smem[];
    const uint32_t sbase = smem_u32(smem);

    const int tid = threadIdx.x;
    const int wid = tid >> 5, lane = tid & 31;
    const int rowBase = blockIdx.y * 128;
    const int colBase = blockIdx.x * 128;

    // warp tiling: 2 (m) x 4 (n) warps; warp tile 64x32
    const int mW = (wid >> 2) * 64;
    const int nW = (wid & 3) * 32;

    float acc[4][4][4];
    #pragma unroll
    for (int i = 0; i < 4; i++)
        #pragma unroll
        for (int j = 0; j < 4; j++)
            #pragma unroll
            for (int q = 0; q < 4; q++) acc[i][j][q] = 0.f;

    // ldmatrix source coordinates (fixed per thread)
    const int aRow = mW + (lane & 15);
    const int aColOff = (lane >> 4) * 8;          // halves
    const int bRow = nW + (lane & 7) + ((lane >> 4) << 3);
    const int bColOff = ((lane >> 3) & 1) * 8;    // halves

    const __half* srcs[4] = {Ahi, Alo, Bhi, Blo};
    const int NC = K >> 5;   // K/32

    // loader: per stage, per operand: 512 16B chunks (128 rows x 4)
    const int ldRow = (tid >> 2) | 0;             // with q offset below
    auto load_stage = [&](int s, int c) {
        const uint32_t dstStage = sbase + s * STAGE;
        #pragma unroll
        for (int a = 0; a < 4; a++) {
            const int tileRow = (a < 2) ? rowBase : colBase;
            const __half* src = srcs[a];
            #pragma unroll
            for (int q = 0; q < 2; q++) {
                int id = tid + 256 * q;           // 0..511
                int row = id >> 2, cc = id & 3;
                const __half* sp = src + (size_t)(tileRow + row) * K + c * 32 + cc * 8;
                uint32_t dp = dstStage + a * TILE + row * SROWB + cc * 16;
                CP_ASYNC16(dp, sp);
            }
        }
        CP_COMMIT();
    };
    (void)ldRow;

    load_stage(0, 0);
    if (NC > 1) load_stage(1, 1);

    for (int c = 0; c < NC; c++) {
        if (c + 1 < NC) { CP_WAIT1(); } else { CP_WAIT0(); }
        __syncthreads();

        const uint32_t st = sbase + (c & 1) * STAGE;

        #pragma unroll
        for (int kk = 0; kk < 32; kk += 16) {
            uint32_t Bh[2][4], Bl[2][4];
            #pragma unroll
            for (int jp = 0; jp < 2; jp++) {
                uint32_t ro = (bRow + jp * 16) * SROWB + (kk + bColOff) * 2;
                LDSM_X4(Bh[jp][0], Bh[jp][1], Bh[jp][2], Bh[jp][3], st + 2 * TILE + ro);
                LDSM_X4(Bl[jp][0], Bl[jp][1], Bl[jp][2], Bl[jp][3], st + 3 * TILE + ro);
            }
            #pragma unroll
            for (int i = 0; i < 4; i++) {
                uint32_t Ah[4], Al[4];
                uint32_t ro = (aRow + i * 16) * SROWB + (kk + aColOff) * 2;
                LDSM_X4(Ah[0], Ah[1], Ah[2], Ah[3], st + ro);
                LDSM_X4(Al[0], Al[1], Al[2], Al[3], st + TILE + ro);
                #pragma unroll
                for (int jp = 0; jp < 2; jp++) {
                    #pragma unroll
                    for (int h = 0; h < 2; h++) {
                        const int j = jp * 2 + h;
                        float* cc2 = acc[i][j];
                        MMA16816(cc2[0], cc2[1], cc2[2], cc2[3],
                                 Ah[0], Ah[1], Ah[2], Ah[3],
                                 Bh[jp][2 * h], Bh[jp][2 * h + 1]);
                        MMA16816(cc2[0], cc2[1], cc2[2], cc2[3],
                                 Ah[0], Ah[1], Ah[2], Ah[3],
                                 Bl[jp][2 * h], Bl[jp][2 * h + 1]);
                        MMA16816(cc2[0], cc2[1], cc2[2], cc2[3],
                                 Al[0], Al[1], Al[2], Al[3],
                                 Bh[jp][2 * h], Bh[jp][2 * h + 1]);
                    }
                }
            }
        }
        __syncthreads();   // compute done before this buffer is reloaded
        if (c + 2 < NC) load_stage(c & 1, c + 2);
    }

    // ---- epilogue ----
    #pragma unroll
    for (int i = 0; i < 4; i++) {
        const int row0 = rowBase + mW + i * 16 + (lane >> 2);
        #pragma unroll
        for (int j = 0; j < 4; j++) {
            const int col = colBase + nW + j * 8 + (lane & 3) * 2;
            if (MODE == 0) {
                float* d0 = Df + (size_t)row0 * N + col;
                float* d1 = Df + (size_t)(row0 + 8) * N + col;
                d0[0] = acc[i][j][0]; d0[1] = acc[i][j][1];
                d1[0] = acc[i][j][2]; d1[1] = acc[i][j][3];
            } else {
                #pragma unroll
                for (int h = 0; h < 2; h++) {
                    const size_t off = (size_t)(row0 + 8 * h) * N + col;
                    float v0 = acc[i][j][2 * h], v1 = acc[i][j][2 * h + 1];
                    __half2 hv = __floats2half2_rn(v0, v1);
                    float2 hf = __half22float2(hv);
                    __half2 lv = __floats2half2_rn(v0 - hf.x, v1 - hf.y);
                    *(__half2*)(Dhi + off) = hv;
                    *(__half2*)(Dlo + off) = lv;
                }
            }
        }
    }
}

// =========================================================================
// Per-image gram (symmetric): 666 upper-triangle dots per 128-d chunk.
// grid (64, 8), atomicAdd both triangles (G pre-zeroed).
// =========================================================================
__global__ __launch_bounds__(256)
void gram_kernel(const float* __restrict__ img, float* __restrict__ G) {
    __shared__ float ch[NS][132];
    const int b = blockIdx.x;
    const int d0 = blockIdx.y * 128;
    const float* base = img + (size_t)b * NS * DIM + d0;

    for (int idx = threadIdx.x; idx < NS * 32; idx += 256) {
        int s = idx >> 5, c4 = idx & 31;
        *(float4*)&ch[s][c4 * 4] = *(const float4*)(base + (size_t)s * DIM + c4 * 4);
    }
    __syncthreads();

    for (int p = threadIdx.x; p < (NS * (NS + 1)) / 2; p += 256) {
        int idx = p, s = 0, rem = NS;
        while (idx >= rem) { idx -= rem; rem--; s++; }
        int s2 = s + idx;
        const float4* r1 = (const float4*)&ch[s][0];
        const float4* r2 = (const float4*)&ch[s2][0];
        float a = 0.f;
        #pragma unroll
        for (int q = 0; q < 32; q++) {
            float4 x = r1[q], y = r2[q];
            a += x.x * y.x + x.y * y.y + x.z * y.z + x.w * y.w;
        }
        atomicAdd(&G[(size_t)b * NS * NS + s * NS + s2], a);
        if (s2 != s) atomicAdd(&G[(size_t)b * NS * NS + s2 * NS + s], a);
    }
}

// =========================================================================
// Caption word norms
// =========================================================================
__global__ __launch_bounds__(1024)
void capnorm_kernel(const float* __restrict__ cap, float* __restrict__ w1) {
    const int i = blockIdx.x, warp = threadIdx.x >> 5, lane = threadIdx.x & 31;
    const float4* row = (const float4*)(cap + (size_t)(i * NL + warp) * DIM);
    float s = 0.f;
    #pragma unroll 8
    for (int q = lane; q < DIM / 4; q += 32) {
        float4 v = row[q];
        s += v.x * v.x + v.y * v.y + v.z * v.z + v.w * v.w;
    }
    #pragma unroll
    for (int o = 16; o; o >>= 1) s += __shfl_down_sync(0xffffffffu, s, o);
    if (lane == 0) w1[i * NL + warp] = sqrtf(s);
}

// =========================================================================
// Per-(image b, caption i) finishing kernel. grid (i=64, b=64), 128 threads.
// =========================================================================
__global__ __launch_bounds__(128)
void pair_kernel(const float* __restrict__ Aarr, const float* __restrict__ Carr,
                 const float* __restrict__ G, const float* __restrict__ w1,
                 const int* __restrict__ cap_lens, float* __restrict__ out) {
    const int i = blockIdx.x;   // caption
    const int b = blockIdx.y;   // image
    const int tid = threadIdx.x;
    const int len = cap_lens[i];

    __shared__ float T[NS][33];
    __shared__ float Cs[NS][33];
    __shared__ float Gs[NS][37];
    __shared__ float Ws[NL][37];
    __shared__ float ninv[NS];
    __shared__ float w12s[NL], w2s[NL];

    const float* Abase = Aarr + (size_t)(b * NS) * CROWS + i * NL;
    const float* Cbase = Carr + (size_t)(b * NS) * CROWS + i * NL;

    for (int idx = tid; idx < NS * NL; idx += 128) {
        int s = idx >> 5, l = idx & 31;
        float v = Abase[(size_t)s * CROWS + l];
        v = (v > 0.f) ? v : 0.1f * v;       // LeakyReLU(0.1)
        if (l >= len) v = 0.f;              // word mask
        T[s][l]  = v;
        Cs[s][l] = Cbase[(size_t)s * CROWS + l];
    }
    for (int idx = tid; idx < NS * NS; idx += 128)
        Gs[idx / NS][idx % NS] = G[(size_t)b * NS * NS + idx];
    __syncthreads();

    if (tid < NS) {
        float sum = 0.f;
        #pragma unroll
        for (int l = 0; l < NL; l++) { float v = T[tid][l]; sum += v * v; }
        ninv[tid] = 9.0f / (sqrtf(sum) + 1e-8f);
    }
    __syncthreads();

    if (tid < NL) {
        const int l = tid;
        float m = -1e30f;
        #pragma unroll
        for (int s = 0; s < NS; s++) m = fmaxf(m, T[s][l] * ninv[s]);
        float sum = 0.f;
        #pragma unroll
        for (int s = 0; s < NS; s++) {
            float e = __expf(T[s][l] * ninv[s] - m);
            Ws[l][s] = e; sum += e;
        }
        float rr = 1.0f / sum;
        #pragma unroll
        for (int s = 0; s < NS; s++) Ws[l][s] *= rr;
    }
    __syncthreads();

    const int warp = tid >> 5, lane = tid & 31;
    for (int l = warp; l < NL; l += 4) {
        float w12 = 0.f, w2 = 0.f;
        for (int s = lane; s < NS; s += 32) {
            float w = Ws[l][s];
            w12 += w * Cs[s][l];
            float v = 0.f;
            #pragma unroll
            for (int s2 = 0; s2 < NS; s2++) v += Gs[s][s2] * Ws[l][s2];
            w2 += w * v;
        }
        #pragma unroll
        for (int o = 16; o; o >>= 1) {
            w12 += __shfl_down_sync(0xffffffffu, w12, o);
            w2  += __shfl_down_sync(0xffffffffu, w2, o);
        }
        if (lane == 0) { w12s[l] = w12; w2s[l] = w2; }
    }
    __syncthreads();

    if (warp == 0) {
        const int l = lane;
        float z;
        if (l < len) {
            float denom = fmaxf(w1[i * NL + l] * sqrtf(fmaxf(w2s[l], 0.f)), 1e-8f);
            z = 6.0f * (w12s[l] / denom);
        } else {
            z = -1e30f;
        }
        float m = z;
        #pragma unroll
        for (int o = 16; o; o >>= 1) m = fmaxf(m, __shfl_xor_sync(0xffffffffu, m, o));
        float e = expf(z - m);
        #pragma unroll
        for (int o = 16; o; o >>= 1) e += __shfl_xor_sync(0xffffffffu, e, o);
        if (lane == 0) out[b * NB + i] = (m + logf(e)) / 6.0f;
    }
}

// =========================================================================
extern "C" void kernel_launch(void* const* d_in, const int* in_sizes, int n_in,
                              void* d_out, int out_size) {
    const float* images   = (const float*)d_in[0];   // (64,36,1024)
    const float* captions = (const float*)d_in[1];   // (64,32,1024)
    const int*   cap_lens = (const int*)d_in[2];     // (64,)
    const float* W_g      = (const float*)d_in[3];   // (1024,1024)
    float* out = (float*)d_out;                      // (64,64)

    static float *pA = nullptr, *pC = nullptr, *pG = nullptr, *pw1 = nullptr;
    static __half *pIhi, *pIlo, *pPhi, *pPlo, *pWhi, *pWlo, *pEhi, *pElo;
    static bool init = false;
    if (!init) {
        cudaGetSymbolAddress((void**)&pA,  g_A);
        cudaGetSymbolAddress((void**)&pC,  g_C);
        cudaGetSymbolAddress((void**)&pG,  g_G);
        cudaGetSymbolAddress((void**)&pw1, g_w1);
        cudaGetSymbolAddress((void**)&pIhi, g_Ihi);
        cudaGetSymbolAddress((void**)&pIlo, g_Ilo);
        cudaGetSymbolAddress((void**)&pPhi, g_Phi);
        cudaGetSymbolAddress((void**)&pPlo, g_Plo);
        cudaGetSymbolAddress((void**)&pWhi, g_Whi);
        cudaGetSymbolAddress((void**)&pWlo, g_Wlo);
        cudaGetSymbolAddress((void**)&pEhi, g_Ehi);
        cudaGetSymbolAddress((void**)&pElo, g_Elo);
        cudaFuncSetAttribute(gemm_tc_kernel<0>, cudaFuncAttributeMaxDynamicSharedMemorySize, GEMM_SMEM);
        cudaFuncSetAttribute(gemm_tc_kernel<1>, cudaFuncAttributeMaxDynamicSharedMemorySize, GEMM_SMEM);
        init = true;
    }

    // 0) split inputs to fp16 hi/lo
    split_kernel<<<(MROWS * DIM / 4 + 255) / 256, 256>>>((const float4*)images, (__half2*)pIhi, (__half2*)pIlo, MROWS * DIM / 4);
    split_kernel<<<(CROWS * DIM / 4 + 255) / 256, 256>>>((const float4*)captions, (__half2*)pPhi, (__half2*)pPlo, CROWS * DIM / 4);
    split_kernel<<<(DIM * DIM / 4 + 255) / 256, 256>>>((const float4*)W_g, (__half2*)pWhi, (__half2*)pWlo, DIM * DIM / 4);

    // 1) E = captions @ W_g^T  -> split fp16 output (2048 x 1024)
    gemm_tc_kernel<1><<<dim3(DIM / 128, CROWS / 128), 256, GEMM_SMEM>>>(
        pPhi, pPlo, pWhi, pWlo, nullptr, pEhi, pElo, CROWS, DIM, DIM);
    // 2) A = images @ E^T       (2304 x 2048) fp32
    gemm_tc_kernel<0><<<dim3(CROWS / 128, MROWS / 128), 256, GEMM_SMEM>>>(
        pIhi, pIlo, pEhi, pElo, pA, nullptr, nullptr, MROWS, CROWS, DIM);
    // 3) C = images @ captions^T (2304 x 2048) fp32
    gemm_tc_kernel<0><<<dim3(CROWS / 128, MROWS / 128), 256, GEMM_SMEM>>>(
        pIhi, pIlo, pPhi, pPlo, pC, nullptr, nullptr, MROWS, CROWS, DIM);
    // 4) per-image grams (zero then atomic-accumulate over 8 D-chunks)
    cudaMemsetAsync(pG, 0, (size_t)NB * NS * NS * sizeof(float));
    gram_kernel<<<dim3(NB, 8), 256>>>(images, pG);
    // 5) caption word norms
    capnorm_kernel<<<NB, 1024>>>(captions, pw1);
    // 6) per-pair finishing
    pair_kernel<<<dim3(NB, NB), 128>>>(pA, pC, pG, pw1, cap_lens, out);
}

// round 8
// speedup vs baseline: 1.0200x; 1.0200x over previous
#include <cuda_runtime.h>
#include <cuda_fp16.h>
#include <math.h>
#include <stdint.h>

// Problem constants
#define DIM   1024
#define NB    64      // n_image == n_caption
#define NS    36      // regions
#define NL    32      // max caption length
#define MROWS (NB*NS)     // 2304 image rows
#define CROWS (NB*NL)     // 2048 caption rows

// ---------------- device scratch (no allocations allowed) ----------------
__device__ float  g_A[MROWS * CROWS];     // attn logits img . E    (2304x2048)
__device__ float  g_C[MROWS * CROWS];     // img . cap dots         (2304x2048)
__device__ float  g_G[NB * NS * NS];      // per-image gram         (64x36x36)
__device__ float  g_w1[CROWS];            // caption word norms     (2048)
__device__ __half g_Ihi[MROWS * DIM], g_Ilo[MROWS * DIM];   // images split
__device__ __half g_Phi[CROWS * DIM], g_Plo[CROWS * DIM];   // captions split
__device__ __half g_Whi[DIM * DIM],   g_Wlo[DIM * DIM];     // W_g split
__device__ __half g_Ehi[CROWS * DIM], g_Elo[CROWS * DIM];   // energy split

__device__ __forceinline__ uint32_t smem_u32(const void* p) {
    uint32_t a;
    asm("{ .reg .u64 t; cvta.to.shared.u64 t, %1; cvt.u32.u64 %0, t; }" : "=r"(a) : "l"(p));
    return a;
}

#define LDSM_X4(r0, r1, r2, r3, addr) \
    asm volatile("ldmatrix.sync.aligned.m8n8.x4.shared.b16 {%0,%1,%2,%3}, [%4];" \
                 : "=r"(r0), "=r"(r1), "=r"(r2), "=r"(r3) : "r"(addr))

#define MMA16816(c0, c1, c2, c3, a0, a1, a2, a3, b0, b1) \
    asm volatile("mma.sync.aligned.m16n8k16.row.col.f32.f16.f16.f32 " \
                 "{%0,%1,%2,%3}, {%4,%5,%6,%7}, {%8,%9}, {%0,%1,%2,%3};" \
                 : "+f"(c0), "+f"(c1), "+f"(c2), "+f"(c3) \
                 : "r"(a0), "r"(a1), "r"(a2), "r"(a3), "r"(b0), "r"(b1))

#define CP_ASYNC16(dst, src) \
    asm volatile("cp.async.cg.shared.global [%0], [%1], 16;" :: "r"(dst), "l"(src))
#define CP_COMMIT() asm volatile("cp.async.commit_group;")
#define CP_WAIT1()  asm volatile("cp.async.wait_group 1;")
#define CP_WAIT0()  asm volatile("cp.async.wait_group 0;")

// =========================================================================
// fp32 -> (hi, lo) fp16 split kernel
// =========================================================================
__global__ __launch_bounds__(256)
void split_kernel(const float4* __restrict__ x, __half2* __restrict__ hi,
                  __half2* __restrict__ lo, int n4) {
    int idx = blockIdx.x * 256 + threadIdx.x;
    if (idx >= n4) return;
    float4 v = x[idx];
    __half2 h0 = __floats2half2_rn(v.x, v.y);
    __half2 h1 = __floats2half2_rn(v.z, v.w);
    float2 f0 = __half22float2(h0);
    float2 f1 = __half22float2(h1);
    hi[2 * idx]     = h0;
    hi[2 * idx + 1] = h1;
    lo[2 * idx]     = __floats2half2_rn(v.x - f0.x, v.y - f0.y);
    lo[2 * idx + 1] = __floats2half2_rn(v.z - f1.x, v.w - f1.y);
}

// =========================================================================
// Split-fp16 tensor-core NT GEMM, cp.async double-buffered.
// D[m][n] = sum_k (Ahi+Alo)[m][k]*(Bhi+Blo)[n][k], dropping lo*lo.
// CTA tile 128x128, 8 warps, warp tile 64x32, K-chunk 64, 2-stage pipeline.
// MMA emission in 3 passes (hh, hl, lh over all 16 accums) to break RAW chains.
// MODE 0: write fp32 D.  MODE 1: write split fp16 (Dhi, Dlo).
// =========================================================================
#define SROWB 144                  // smem row stride bytes (72 halves)
#define TILE  (128 * SROWB)        // 18432 B per operand tile
#define STAGE (4 * TILE)           // Ah, Al, Bh, Bl
#define GEMM_SMEM (2 * STAGE)      // 147456 B

template<int MODE>
__global__ __launch_bounds__(256, 1)
void gemm_tc_kernel(const __half* __restrict__ Ahi, const __half* __restrict__ Alo,
                    const __half* __restrict__ Bhi, const __half* __restrict__ Blo,
                    float* __restrict__ Df, __half* __restrict__ Dhi, __half* __restrict__ Dlo,
                    int M, int N, int K) {
    extern __shared__ char smem[];
    const uint32_t sbase = smem_u32(smem);

    const int tid = threadIdx.x;
    const int wid = tid >> 5, lane = tid & 31;
    const int rowBase = blockIdx.y * 128;
    const int colBase = blockIdx.x * 128;

    // warp tiling: 2 (m) x 4 (n) warps; warp tile 64x32
    const int mW = (wid >> 2) * 64;
    const int nW = (wid & 3) * 32;

    float acc[4][4][4];
    #pragma unroll
    for (int i = 0; i < 4; i++)
        #pragma unroll
        for (int j = 0; j < 4; j++)
            #pragma unroll
            for (int q = 0; q < 4; q++) acc[i][j][q] = 0.f;

    // ldmatrix source coordinates (fixed per thread)
    const int aRow = mW + (lane & 15);
    const int aColOff = (lane >> 4) * 8;
    const int bRow = nW + (lane & 7) + ((lane >> 4) << 3);
    const int bColOff = ((lane >> 3) & 1) * 8;

    const __half* srcs[4] = {Ahi, Alo, Bhi, Blo};
    const int NC = K >> 6;   // K/64

    // loader: stage s <- K-chunk c; per array: 4x 16B per thread
    auto load_stage = [&](int s, int c) {
        const uint32_t dstStage = sbase + s * STAGE;
        #pragma unroll
        for (int a = 0; a < 4; a++) {
            const int tileRow = (a < 2) ? rowBase : colBase;
            const __half* src = srcs[a];
            #pragma unroll
            for (int q = 0; q < 4; q++) {
                int id = tid + 256 * q;          // 0..1023
                int row = id >> 3, cc = id & 7;
                const __half* sp = src + (size_t)(tileRow + row) * K + c * 64 + cc * 8;
                uint32_t dp = dstStage + a * TILE + row * SROWB + cc * 16;
                CP_ASYNC16(dp, sp);
            }
        }
        CP_COMMIT();
    };

    load_stage(0, 0);
    if (NC > 1) load_stage(1, 1);

    for (int c = 0; c < NC; c++) {
        if (c + 1 < NC) { CP_WAIT1(); } else { CP_WAIT0(); }
        __syncthreads();

        const uint32_t st = sbase + (c & 1) * STAGE;

        #pragma unroll
        for (int kk = 0; kk < 64; kk += 16) {
            uint32_t Ah[4][4], Al[4][4], Bh[2][4], Bl[2][4];
            #pragma unroll
            for (int i = 0; i < 4; i++) {
                uint32_t ro = (aRow + i * 16) * SROWB + (kk + aColOff) * 2;
                LDSM_X4(Ah[i][0], Ah[i][1], Ah[i][2], Ah[i][3], st + ro);
                LDSM_X4(Al[i][0], Al[i][1], Al[i][2], Al[i][3], st + TILE + ro);
            }
            #pragma unroll
            for (int jp = 0; jp < 2; jp++) {
                uint32_t ro = (bRow + jp * 16) * SROWB + (kk + bColOff) * 2;
                LDSM_X4(Bh[jp][0], Bh[jp][1], Bh[jp][2], Bh[jp][3], st + 2 * TILE + ro);
                LDSM_X4(Bl[jp][0], Bl[jp][1], Bl[jp][2], Bl[jp][3], st + 3 * TILE + ro);
            }
            // Pass 1: hi*hi into all 16 accumulators (no RAW back-to-back)
            #pragma unroll
            for (int i = 0; i < 4; i++)
                #pragma unroll
                for (int jp = 0; jp < 2; jp++)
                    #pragma unroll
                    for (int h = 0; h < 2; h++) {
                        float* cc2 = acc[i][jp * 2 + h];
                        MMA16816(cc2[0], cc2[1], cc2[2], cc2[3],
                                 Ah[i][0], Ah[i][1], Ah[i][2], Ah[i][3],
                                 Bh[jp][2 * h], Bh[jp][2 * h + 1]);
                    }
            // Pass 2: hi*lo
            #pragma unroll
            for (int i = 0; i < 4; i++)
                #pragma unroll
                for (int jp = 0; jp < 2; jp++)
                    #pragma unroll
                    for (int h = 0; h < 2; h++) {
                        float* cc2 = acc[i][jp * 2 + h];
                        MMA16816(cc2[0], cc2[1], cc2[2], cc2[3],
                                 Ah[i][0], Ah[i][1], Ah[i][2], Ah[i][3],
                                 Bl[jp][2 * h], Bl[jp][2 * h + 1]);
                    }
            // Pass 3: lo*hi
            #pragma unroll
            for (int i = 0; i < 4; i++)
                #pragma unroll
                for (int jp = 0; jp < 2; jp++)
                    #pragma unroll
                    for (int h = 0; h < 2; h++) {
                        float* cc2 = acc[i][jp * 2 + h];
                        MMA16816(cc2[0], cc2[1], cc2[2], cc2[3],
                                 Al[i][0], Al[i][1], Al[i][2], Al[i][3],
                                 Bh[jp][2 * h], Bh[jp][2 * h + 1]);
                    }
        }
        __syncthreads();   // compute done before this buffer is reloaded
        if (c + 2 < NC) load_stage(c & 1, c + 2);
    }

    // ---- epilogue ----
    #pragma unroll
    for (int i = 0; i < 4; i++) {
        const int row0 = rowBase + mW + i * 16 + (lane >> 2);
        #pragma unroll
        for (int j = 0; j < 4; j++) {
            const int col = colBase + nW + j * 8 + (lane & 3) * 2;
            if (MODE == 0) {
                float* d0 = Df + (size_t)row0 * N + col;
                float* d1 = Df + (size_t)(row0 + 8) * N + col;
                d0[0] = acc[i][j][0]; d0[1] = acc[i][j][1];
                d1[0] = acc[i][j][2]; d1[1] = acc[i][j][3];
            } else {
                #pragma unroll
                for (int h = 0; h < 2; h++) {
                    const size_t off = (size_t)(row0 + 8 * h) * N + col;
                    float v0 = acc[i][j][2 * h], v1 = acc[i][j][2 * h + 1];
                    __half2 hv = __floats2half2_rn(v0, v1);
                    float2 hf = __half22float2(hv);
                    __half2 lv = __floats2half2_rn(v0 - hf.x, v1 - hf.y);
                    *(__half2*)(Dhi + off) = hv;
                    *(__half2*)(Dlo + off) = lv;
                }
            }
        }
    }
}

// =========================================================================
// Per-image gram (symmetric): 666 upper-triangle dots per 128-d chunk.
// grid (64, 8), atomicAdd both triangles (G pre-zeroed).
// =========================================================================
__global__ __launch_bounds__(256)
void gram_kernel(const float* __restrict__ img, float* __restrict__ G) {
    __shared__ float ch[NS][132];
    const int b = blockIdx.x;
    const int d0 = blockIdx.y * 128;
    const float* base = img + (size_t)b * NS * DIM + d0;

    for (int idx = threadIdx.x; idx < NS * 32; idx += 256) {
        int s = idx >> 5, c4 = idx & 31;
        *(float4*)&ch[s][c4 * 4] = *(const float4*)(base + (size_t)s * DIM + c4 * 4);
    }
    __syncthreads();

    for (int p = threadIdx.x; p < (NS * (NS + 1)) / 2; p += 256) {
        int idx = p, s = 0, rem = NS;
        while (idx >= rem) { idx -= rem; rem--; s++; }
        int s2 = s + idx;
        const float4* r1 = (const float4*)&ch[s][0];
        const float4* r2 = (const float4*)&ch[s2][0];
        float a = 0.f;
        #pragma unroll
        for (int q = 0; q < 32; q++) {
            float4 x = r1[q], y = r2[q];
            a += x.x * y.x + x.y * y.y + x.z * y.z + x.w * y.w;
        }
        atomicAdd(&G[(size_t)b * NS * NS + s * NS + s2], a);
        if (s2 != s) atomicAdd(&G[(size_t)b * NS * NS + s2 * NS + s], a);
    }
}

// =========================================================================
// Caption word norms
// =========================================================================
__global__ __launch_bounds__(1024)
void capnorm_kernel(const float* __restrict__ cap, float* __restrict__ w1) {
    const int i = blockIdx.x, warp = threadIdx.x >> 5, lane = threadIdx.x & 31;
    const float4* row = (const float4*)(cap + (size_t)(i * NL + warp) * DIM);
    float s = 0.f;
    #pragma unroll 8
    for (int q = lane; q < DIM / 4; q += 32) {
        float4 v = row[q];
        s += v.x * v.x + v.y * v.y + v.z * v.z + v.w * v.w;
    }
    #pragma unroll
    for (int o = 16; o; o >>= 1) s += __shfl_down_sync(0xffffffffu, s, o);
    if (lane == 0) w1[i * NL + warp] = sqrtf(s);
}

// =========================================================================
// Per-(image b, caption i) finishing kernel. grid (i=64, b=64), 128 threads.
// =========================================================================
__global__ __launch_bounds__(128)
void pair_kernel(const float* __restrict__ Aarr, const float* __restrict__ Carr,
                 const float* __restrict__ G, const float* __restrict__ w1,
                 const int* __restrict__ cap_lens, float* __restrict__ out) {
    const int i = blockIdx.x;   // caption
    const int b = blockIdx.y;   // image
    const int tid = threadIdx.x;
    const int len = cap_lens[i];

    __shared__ float T[NS][33];
    __shared__ float Cs[NS][33];
    __shared__ float Gs[NS][37];
    __shared__ float Ws[NL][37];
    __shared__ float ninv[NS];
    __shared__ float w12s[NL], w2s[NL];

    const float* Abase = Aarr + (size_t)(b * NS) * CROWS + i * NL;
    const float* Cbase = Carr + (size_t)(b * NS) * CROWS + i * NL;

    for (int idx = tid; idx < NS * NL; idx += 128) {
        int s = idx >> 5, l = idx & 31;
        float v = Abase[(size_t)s * CROWS + l];
        v = (v > 0.f) ? v : 0.1f * v;       // LeakyReLU(0.1)
        if (l >= len) v = 0.f;              // word mask
        T[s][l]  = v;
        Cs[s][l] = Cbase[(size_t)s * CROWS + l];
    }
    for (int idx = tid; idx < NS * NS; idx += 128)
        Gs[idx / NS][idx % NS] = G[(size_t)b * NS * NS + idx];
    __syncthreads();

    if (tid < NS) {
        float sum = 0.f;
        #pragma unroll
        for (int l = 0; l < NL; l++) { float v = T[tid][l]; sum += v * v; }
        ninv[tid] = 9.0f / (sqrtf(sum) + 1e-8f);
    }
    __syncthreads();

    if (tid < NL) {
        const int l = tid;
        float m = -1e30f;
        #pragma unroll
        for (int s = 0; s < NS; s++) m = fmaxf(m, T[s][l] * ninv[s]);
        float sum = 0.f;
        #pragma unroll
        for (int s = 0; s < NS; s++) {
            float e = __expf(T[s][l] * ninv[s] - m);
            Ws[l][s] = e; sum += e;
        }
        float rr = 1.0f / sum;
        #pragma unroll
        for (int s = 0; s < NS; s++) Ws[l][s] *= rr;
    }
    __syncthreads();

    const int warp = tid >> 5, lane = tid & 31;
    for (int l = warp; l < NL; l += 4) {
        float w12 = 0.f, w2 = 0.f;
        for (int s = lane; s < NS; s += 32) {
            float w = Ws[l][s];
            w12 += w * Cs[s][l];
            float v = 0.f;
            #pragma unroll
            for (int s2 = 0; s2 < NS; s2++) v += Gs[s][s2] * Ws[l][s2];
            w2 += w * v;
        }
        #pragma unroll
        for (int o = 16; o; o >>= 1) {
            w12 += __shfl_down_sync(0xffffffffu, w12, o);
            w2  += __shfl_down_sync(0xffffffffu, w2, o);
        }
        if (lane == 0) { w12s[l] = w12; w2s[l] = w2; }
    }
    __syncthreads();

    if (warp == 0) {
        const int l = lane;
        float z;
        if (l < len) {
            float denom = fmaxf(w1[i * NL + l] * sqrtf(fmaxf(w2s[l], 0.f)), 1e-8f);
            z = 6.0f * (w12s[l] / denom);
        } else {
            z = -1e30f;
        }
        float m = z;
        #pragma unroll
        for (int o = 16; o; o >>= 1) m = fmaxf(m, __shfl_xor_sync(0xffffffffu, m, o));
        float e = expf(z - m);
        #pragma unroll
        for (int o = 16; o; o >>= 1) e += __shfl_xor_sync(0xffffffffu, e, o);
        if (lane == 0) out[b * NB + i] = (m + logf(e)) / 6.0f;
    }
}

// =========================================================================
extern "C" void kernel_launch(void* const* d_in, const int* in_sizes, int n_in,
                              void* d_out, int out_size) {
    const float* images   = (const float*)d_in[0];   // (64,36,1024)
    const float* captions = (const float*)d_in[1];   // (64,32,1024)
    const int*   cap_lens = (const int*)d_in[2];     // (64,)
    const float* W_g      = (const float*)d_in[3];   // (1024,1024)
    float* out = (float*)d_out;                      // (64,64)

    static float *pA = nullptr, *pC = nullptr, *pG = nullptr, *pw1 = nullptr;
    static __half *pIhi, *pIlo, *pPhi, *pPlo, *pWhi, *pWlo, *pEhi, *pElo;
    static bool init = false;
    if (!init) {
        cudaGetSymbolAddress((void**)&pA,  g_A);
        cudaGetSymbolAddress((void**)&pC,  g_C);
        cudaGetSymbolAddress((void**)&pG,  g_G);
        cudaGetSymbolAddress((void**)&pw1, g_w1);
        cudaGetSymbolAddress((void**)&pIhi, g_Ihi);
        cudaGetSymbolAddress((void**)&pIlo, g_Ilo);
        cudaGetSymbolAddress((void**)&pPhi, g_Phi);
        cudaGetSymbolAddress((void**)&pPlo, g_Plo);
        cudaGetSymbolAddress((void**)&pWhi, g_Whi);
        cudaGetSymbolAddress((void**)&pWlo, g_Wlo);
        cudaGetSymbolAddress((void**)&pEhi, g_Ehi);
        cudaGetSymbolAddress((void**)&pElo, g_Elo);
        cudaFuncSetAttribute(gemm_tc_kernel<0>, cudaFuncAttributeMaxDynamicSharedMemorySize, GEMM_SMEM);
        cudaFuncSetAttribute(gemm_tc_kernel<1>, cudaFuncAttributeMaxDynamicSharedMemorySize, GEMM_SMEM);
        init = true;
    }

    // 0) split inputs to fp16 hi/lo
    split_kernel<<<(MROWS * DIM / 4 + 255) / 256, 256>>>((const float4*)images, (__half2*)pIhi, (__half2*)pIlo, MROWS * DIM / 4);
    split_kernel<<<(CROWS * DIM / 4 + 255) / 256, 256>>>((const float4*)captions, (__half2*)pPhi, (__half2*)pPlo, CROWS * DIM / 4);
    split_kernel<<<(DIM * DIM / 4 + 255) / 256, 256>>>((const float4*)W_g, (__half2*)pWhi, (__half2*)pWlo, DIM * DIM / 4);

    // 1) E = captions @ W_g^T  -> split fp16 output (2048 x 1024)
    gemm_tc_kernel<1><<<dim3(DIM / 128, CROWS / 128), 256, GEMM_SMEM>>>(
        pPhi, pPlo, pWhi, pWlo, nullptr, pEhi, pElo, CROWS, DIM, DIM);
    // 2) A = images @ E^T       (2304 x 2048) fp32
    gemm_tc_kernel<0><<<dim3(CROWS / 128, MROWS / 128), 256, GEMM_SMEM>>>(
        pIhi, pIlo, pEhi, pElo, pA, nullptr, nullptr, MROWS, CROWS, DIM);
    // 3) C = images @ captions^T (2304 x 2048) fp32
    gemm_tc_kernel<0><<<dim3(CROWS / 128, MROWS / 128), 256, GEMM_SMEM>>>(
        pIhi, pIlo, pPhi, pPlo, pC, nullptr, nullptr, MROWS, CROWS, DIM);
    // 4) per-image grams (zero then atomic-accumulate over 8 D-chunks)
    cudaMemsetAsync(pG, 0, (size_t)NB * NS * NS * sizeof(float));
    gram_kernel<<<dim3(NB, 8), 256>>>(images, pG);
    // 5) caption word norms
    capnorm_kernel<<<NB, 1024>>>(captions, pw1);
    // 6) per-pair finishing
    pair_kernel<<<dim3(NB, NB), 128>>>(pA, pC, pG, pw1, cap_lens, out);
}